// round 10
// baseline (speedup 1.0000x reference)
#include <cuda_runtime.h>
#include <cuda_fp16.h>
#include <math_constants.h>
#include <stdint.h>

#define BATCH 4
#define SEQ   2048
#define DM    1024
#define MROWS (BATCH * SEQ)

#define LO_SCALE  2048.0f
#define INV_LO    (1.0f / 2048.0f)

// ---- GEMM tiling: 128x128 CTA tile, 16 warps (32x32 warp tile) ---------------
#define TM 128
#define TN 128
#define BK 64                         // f16 elems per K-chunk (128 bytes/row)
#define TILE_BYTES (128 * 128)        // 16 KB per operand tile
#define STAGE_BYTES (4 * TILE_BYTES)  // Ahi,Alo,Bhi,Blo = 64 KB
#define NSTAGE 3
#define SMEM_DYN (NSTAGE * STAGE_BYTES)   // 192 KB
#define NTHREADS 512

typedef __half h16;

// ---- scratch (static __device__: allocation-free) ------------------------------
#define AL1K __align__(1024)
__device__ AL1K h16   g_xh [MROWS * DM];
__device__ AL1K h16   g_xl [MROWS * DM];
__device__ AL1K h16   g_wAh[2 * DM * DM];   // [Wk ; Wo^T] split hi
__device__ AL1K h16   g_wAl[2 * DM * DM];
__device__ AL1K h16   g_wBh[2 * DM * DM];   // [Wq ; Wv] split hi
__device__ AL1K h16   g_wBl[2 * DM * DM];
__device__ AL1K h16   g_gh [2 * DM * DM];   // [GT ; HT] split hi
__device__ AL1K h16   g_gl [2 * DM * DM];
__device__ AL1K h16   g_qxh[(size_t)2 * MROWS * DM];  // [QG ; XH] split hi
__device__ AL1K h16   g_qxl[(size_t)2 * MROWS * DM];
__device__ AL1K h16   g_xth[MROWS * DM];    // XH^T per batch [B][D][S]
__device__ AL1K h16   g_xtl[MROWS * DM];
__device__ AL1K float g_p  [(size_t)BATCH * SEQ * SEQ];
__device__ AL1K h16   g_ph [(size_t)BATCH * SEQ * SEQ];
__device__ AL1K h16   g_pl [(size_t)BATCH * SEQ * SEQ];
__device__ AL1K float g_w2 [DM];
__device__ AL1K float g_v  [MROWS];
__device__ AL1K float g_rb [DM];

// ---- PTX helpers -----------------------------------------------------------------
__device__ __forceinline__ uint32_t s2u(const void* p) {
    uint32_t a;
    asm("{ .reg .u64 t; cvta.to.shared.u64 t, %1; cvt.u32.u64 %0, t; }" : "=r"(a) : "l"(p));
    return a;
}
__device__ __forceinline__ void cp16(uint32_t saddr, const void* gaddr) {
    asm volatile("cp.async.cg.shared.global [%0], [%1], 16;" :: "r"(saddr), "l"(gaddr));
}
__device__ __forceinline__ void cp_commit() { asm volatile("cp.async.commit_group;"); }
__device__ __forceinline__ void cp_wait2()  { asm volatile("cp.async.wait_group 2;" ::: "memory"); }

__device__ __forceinline__ void ldm4(uint32_t* r, uint32_t addr) {
    asm volatile("ldmatrix.sync.aligned.m8n8.x4.shared.b16 {%0,%1,%2,%3}, [%4];"
                 : "=r"(r[0]), "=r"(r[1]), "=r"(r[2]), "=r"(r[3]) : "r"(addr));
}
__device__ __forceinline__ void mma_f32(float* c, const uint32_t* a, const uint32_t* b) {
    asm volatile(
        "mma.sync.aligned.m16n8k16.row.col.f32.f16.f16.f32 "
        "{%0,%1,%2,%3}, {%4,%5,%6,%7}, {%8,%9}, {%0,%1,%2,%3};"
        : "+f"(c[0]), "+f"(c[1]), "+f"(c[2]), "+f"(c[3])
        : "r"(a[0]), "r"(a[1]), "r"(a[2]), "r"(a[3]), "r"(b[0]), "r"(b[1]));
}
__device__ __forceinline__ void mma_f16(uint32_t* c, const uint32_t* a, const uint32_t* b) {
    asm volatile(
        "mma.sync.aligned.m16n8k16.row.col.f16.f16.f16.f16 "
        "{%0,%1}, {%2,%3,%4,%5}, {%6,%7}, {%0,%1};"
        : "+r"(c[0]), "+r"(c[1])
        : "r"(a[0]), "r"(a[1]), "r"(a[2]), "r"(a[3]), "r"(b[0]), "r"(b[1]));
}
__device__ __forceinline__ uint32_t pk2(float a, float b) {
    __half2 t = __floats2half2_rn(a, b);
    return *reinterpret_cast<uint32_t*>(&t);
}

// ============================================================================
// Tensor-core GEMM, 512 threads, 16 warps, warp tile 32x32.
//   C[M,N] = scale*((Ahi+Alo/2048)[M,K] @ ((Bhi+Blo/2048)[N,K])^T)+bias
//   NTERM=3: AhBh(f32) + AhBl(f16) + AlBh(f16)
//   NTERM=2: AhBh + AlBh   (B-lo unused, not even loaded)
//   NTERM=1: AhBh only     (both lo tiles unused)
//   OUTMODE 0: fp32 out. OUTMODE 1: f16 split out (lo x2048).
//   CAUSAL: skip tiles above diagonal.  PVLIM: K truncated.  REVY: heavy first.
// ============================================================================
template<int OUTMODE, bool HAS_BIAS, bool CAUSAL, bool PVLIM, bool REVY, int NTERM>
__global__ __launch_bounds__(NTHREADS, 1)
void tc_gemm(const h16* __restrict__ Ah, const h16* __restrict__ Al,
             const h16* __restrict__ Bh, const h16* __restrict__ Bl,
             const float* __restrict__ bias,
             float* __restrict__ Cf, h16* __restrict__ Ch, h16* __restrict__ Cl,
             int Kfull, int ldA, int ldB, int ldC, float scale,
             size_t sA, size_t sB, size_t sC)
{
    const int bmi = REVY ? (gridDim.y - 1 - blockIdx.y) : blockIdx.y;
    const int m0 = bmi * TM;
    const int n0 = blockIdx.x * TN;
    if (CAUSAL && n0 > m0) return;

    const int z = blockIdx.z;
    Ah += (size_t)z * sA;  Al += (size_t)z * sA;
    Bh += (size_t)z * sB;  Bl += (size_t)z * sB;

    extern __shared__ char dsm[];
    const uint32_t smem = s2u(dsm);

    const int tid  = threadIdx.x;
    const int wid  = tid >> 5;
    const int lane = tid & 31;
    const int wm   = wid & 3;    // 4 warp-rows  (32 M each)
    const int wn   = wid >> 2;   // 4 warp-cols  (32 N each)

    const int nchunk = PVLIM ? (m0 + TM) / BK : Kfull / BK;

    // ---- loader: 512 rows (4 tiles x 128), ONE row per thread, 8 segs --------
    const int ltile = tid >> 7;        // 0:Ah 1:Al 2:Bh 3:Bl
    const int lr    = tid & 127;
    const bool do_load = !((NTERM < 2 && ltile == 1) || (NTERM < 3 && ltile == 3));
    const h16* lbase = (ltile == 0) ? Ah : (ltile == 1) ? Al : (ltile == 2) ? Bh : Bl;
    const int  loff  = (ltile < 2) ? m0 : n0;
    const int  lld   = (ltile < 2) ? ldA : ldB;
    const char* gp   = (const char*)(lbase + (size_t)(loff + lr) * lld);
    const uint32_t sbase = (uint32_t)(ltile * TILE_BYTES + lr * 128);
    const uint32_t swz   = (uint32_t)(lr & 7);

    auto load_stage = [&](int slot, int chunk) {
        if (chunk < nchunk && do_load) {
            const uint32_t s0 = smem + slot * STAGE_BYTES + sbase;
            const char* g = gp + (size_t)chunk * 128;
            #pragma unroll
            for (uint32_t seg = 0; seg < 8; seg++)
                cp16(s0 + ((seg ^ swz) << 4), g + seg * 16);
        }
        cp_commit();
    };

    float    accf[2][4][4];
    uint32_t acch[2][4][2];
    #pragma unroll
    for (int a = 0; a < 2; a++)
        #pragma unroll
        for (int b = 0; b < 4; b++) {
            #pragma unroll
            for (int c = 0; c < 4; c++) accf[a][b][c] = 0.f;
            acch[a][b][0] = 0u; acch[a][b][1] = 0u;
        }

    load_stage(0, 0);
    load_stage(1, 1);
    load_stage(2, 2);

    const int a_r  = lane & 15;
    const int a_kh = lane >> 4;
    const int b_nl = ((lane >> 4) & 1) * 8 + (lane & 7);
    const int b_kh = (lane >> 3) & 1;

    for (int i = 0; i < nchunk; i++) {
        cp_wait2();
        __syncthreads();
        const uint32_t s0 = smem + (i % 3) * STAGE_BYTES;

        #pragma unroll
        for (int kk = 0; kk < 4; kk++) {
            uint32_t ahf[2][4], alf[2][4], bhf[2][4], blf[2][4];
            #pragma unroll
            for (int mt = 0; mt < 2; mt++) {
                const int row = wm * 32 + mt * 16 + a_r;
                const int seg = kk * 2 + a_kh;
                const uint32_t off = (uint32_t)(row * 128 + ((seg ^ (row & 7)) << 4));
                ldm4(ahf[mt], s0 + 0 * TILE_BYTES + off);
                if (NTERM >= 2) ldm4(alf[mt], s0 + 1 * TILE_BYTES + off);
            }
            #pragma unroll
            for (int p = 0; p < 2; p++) {
                const int row = wn * 32 + p * 16 + b_nl;
                const int seg = kk * 2 + b_kh;
                const uint32_t off = (uint32_t)(row * 128 + ((seg ^ (row & 7)) << 4));
                ldm4(bhf[p], s0 + 2 * TILE_BYTES + off);
                if (NTERM >= 3) ldm4(blf[p], s0 + 3 * TILE_BYTES + off);
            }
            // main term (f32 acc)
            #pragma unroll
            for (int mt = 0; mt < 2; mt++)
                #pragma unroll
                for (int nt = 0; nt < 4; nt++)
                    mma_f32(accf[mt][nt], ahf[mt], &bhf[nt >> 1][(nt & 1) * 2]);
            // correction terms (f16 acc; lo operands pre-scaled x2048)
            if (NTERM >= 3) {
                #pragma unroll
                for (int mt = 0; mt < 2; mt++)
                    #pragma unroll
                    for (int nt = 0; nt < 4; nt++)
                        mma_f16(acch[mt][nt], ahf[mt], &blf[nt >> 1][(nt & 1) * 2]);
            }
            if (NTERM >= 2) {
                #pragma unroll
                for (int mt = 0; mt < 2; mt++)
                    #pragma unroll
                    for (int nt = 0; nt < 4; nt++)
                        mma_f16(acch[mt][nt], alf[mt], &bhf[nt >> 1][(nt & 1) * 2]);
            }
        }
        __syncthreads();
        load_stage(i % 3, i + 3);
    }

    #pragma unroll
    for (int mt = 0; mt < 2; mt++) {
        #pragma unroll
        for (int h = 0; h < 2; h++) {
            const int row = m0 + wm * 32 + mt * 16 + (lane >> 2) + 8 * h;
            #pragma unroll
            for (int nt = 0; nt < 4; nt++) {
                const int col = n0 + wn * 32 + nt * 8 + (lane & 3) * 2;
                float c0, c1;
                if (NTERM >= 2) {
                    const __half2 hc = *reinterpret_cast<const __half2*>(&acch[mt][nt][h]);
                    c0 = __low2float(hc)  * INV_LO;
                    c1 = __high2float(hc) * INV_LO;
                } else { c0 = 0.f; c1 = 0.f; }
                float v0 = (accf[mt][nt][2 * h + 0] + c0) * scale;
                float v1 = (accf[mt][nt][2 * h + 1] + c1) * scale;
                if (HAS_BIAS) {
                    const float2 bb = *reinterpret_cast<const float2*>(bias + col);
                    v0 += bb.x; v1 += bb.y;
                }
                if (OUTMODE == 0) {
                    *reinterpret_cast<float2*>(
                        Cf + (size_t)z * sC + (size_t)row * ldC + col) =
                        make_float2(v0, v1);
                } else {
                    float h0 = __half2float(__float2half_rn(v0));
                    float h1 = __half2float(__float2half_rn(v1));
                    *reinterpret_cast<uint32_t*>(
                        Ch + (size_t)z * sC + (size_t)row * ldC + col) = pk2(h0, h1);
                    *reinterpret_cast<uint32_t*>(
                        Cl + (size_t)z * sC + (size_t)row * ldC + col) =
                        pk2((v0 - h0) * LO_SCALE, (v1 - h1) * LO_SCALE);
                }
            }
        }
    }
}

// ============================================================================
// prep kernels (all lo outputs pre-scaled x2048)
// ============================================================================
__global__ void split_kernel(const float* __restrict__ in,
                             h16* __restrict__ oh, h16* __restrict__ ol, int n)
{
    int i = blockIdx.x * blockDim.x + threadIdx.x;
    if (i >= n) return;
    float v = in[i];
    h16 h = __float2half_rn(v);
    oh[i] = h;
    ol[i] = __float2half_rn((v - __half2float(h)) * LO_SCALE);
}

__global__ void tsplit_kernel(const float* __restrict__ in,
                              h16* __restrict__ oh, h16* __restrict__ ol,
                              int R, int C)
{
    __shared__ float t[32][33];
    const int c0 = blockIdx.x * 32, r0 = blockIdx.y * 32;
    const int tx = threadIdx.x, ty = threadIdx.y;
    #pragma unroll
    for (int k = 0; k < 4; k++)
        t[ty + 8 * k][tx] = in[(size_t)(r0 + ty + 8 * k) * C + c0 + tx];
    __syncthreads();
    #pragma unroll
    for (int k = 0; k < 4; k++) {
        float v = t[tx][ty + 8 * k];
        h16 h = __float2half_rn(v);
        size_t o = (size_t)(c0 + ty + 8 * k) * R + r0 + tx;
        oh[o] = h;
        ol[o] = __float2half_rn((v - __half2float(h)) * LO_SCALE);
    }
}

// XH transpose+split: reads XH = hi + lo/2048 at rows [MROWS + b*SEQ + s], ld=DM
__global__ void txsplit_kernel(const h16* __restrict__ qh, const h16* __restrict__ ql,
                               h16* __restrict__ oh, h16* __restrict__ ol)
{
    __shared__ float t[32][33];
    const int z = blockIdx.z;
    const int d0 = blockIdx.x * 32, s0 = blockIdx.y * 32;
    const int tx = threadIdx.x, ty = threadIdx.y;
    #pragma unroll
    for (int k = 0; k < 4; k++) {
        size_t idx = (size_t)(MROWS + z * SEQ + s0 + ty + 8 * k) * DM + d0 + tx;
        t[ty + 8 * k][tx] = __half2float(qh[idx]) + __half2float(ql[idx]) * INV_LO;
    }
    __syncthreads();
    #pragma unroll
    for (int k = 0; k < 4; k++) {
        float v = t[tx][ty + 8 * k];
        h16 h = __float2half_rn(v);
        size_t o = (size_t)z * DM * SEQ + (size_t)(d0 + ty + 8 * k) * SEQ + s0 + tx;
        oh[o] = h;
        ol[o] = __float2half_rn((v - __half2float(h)) * LO_SCALE);
    }
}

__global__ void wkbq_kernel(const float* __restrict__ Wk, const float* __restrict__ bq,
                            float* __restrict__ w2)
{
    int w = (blockIdx.x * blockDim.x + threadIdx.x) >> 5;
    int lane = threadIdx.x & 31;
    if (w >= DM) return;
    float s = 0.f;
    for (int e = lane; e < DM; e += 32) s += Wk[(size_t)w * DM + e] * bq[e];
    #pragma unroll
    for (int o = 16; o > 0; o >>= 1) s += __shfl_down_sync(0xffffffffu, s, o);
    if (lane == 0) w2[w] = s;
}

__global__ void rb_kernel(const float* __restrict__ Wo, const float* __restrict__ bv,
                          const float* __restrict__ bo, float* __restrict__ rb)
{
    int d = blockIdx.x * blockDim.x + threadIdx.x;
    if (d >= DM) return;
    float s = 0.f;
    for (int e = 0; e < DM; e++) s += bv[e] * Wo[(size_t)e * DM + d];
    rb[d] = s + bo[d];
}

__global__ void vvec_kernel(const float* __restrict__ x, const float* __restrict__ w2,
                            float* __restrict__ v)
{
    int w = (blockIdx.x * blockDim.x + threadIdx.x) >> 5;
    int lane = threadIdx.x & 31;
    if (w >= MROWS) return;
    float s = 0.f;
    for (int d = lane; d < DM; d += 32) s += x[(size_t)w * DM + d] * w2[d];
    #pragma unroll
    for (int o = 16; o > 0; o >>= 1) s += __shfl_down_sync(0xffffffffu, s, o);
    if (lane == 0) v[w] = s;
}

__global__ __launch_bounds__(256)
void softmax_split_kernel(float* __restrict__ P, const float* __restrict__ V,
                          h16* __restrict__ Ph, h16* __restrict__ Pl)
{
    const int rowi = blockIdx.x;
    const int b = rowi / SEQ, q = rowi % SEQ;
    const size_t off = (size_t)b * SEQ * SEQ + (size_t)q * SEQ;
    float* p = P + off;
    const float* vv = V + (size_t)b * SEQ;
    h16* ph = Ph + off;
    h16* pl = Pl + off;
    const int n = q + 1;

    __shared__ float red[256];
    const int tid = threadIdx.x;

    float mx = -CUDART_INF_F;
    for (int k = tid; k < n; k += 256) mx = fmaxf(mx, p[k] + 0.125f * vv[k]);
    red[tid] = mx; __syncthreads();
    #pragma unroll
    for (int s = 128; s > 0; s >>= 1) {
        if (tid < s) red[tid] = fmaxf(red[tid], red[tid + s]);
        __syncthreads();
    }
    mx = red[0]; __syncthreads();

    float sum = 0.f;
    for (int k = tid; k < n; k += 256) {
        float e = expf(p[k] + 0.125f * vv[k] - mx);
        p[k] = e;
        sum += e;
    }
    red[tid] = sum; __syncthreads();
    #pragma unroll
    for (int s = 128; s > 0; s >>= 1) {
        if (tid < s) red[tid] += red[tid + s];
        __syncthreads();
    }
    const float inv = 1.f / red[0];

    for (int k = tid; k < n; k += 256) {
        float w = p[k] * inv;
        h16 h = __float2half_rn(w);
        ph[k] = h;
        pl[k] = __float2half_rn((w - __half2float(h)) * LO_SCALE);
    }
    const int fillEnd = ((q >> 7) + 1) << 7;
    for (int k = n + tid; k < fillEnd; k += 256) {
        ph[k] = __float2half_rn(0.f);
        pl[k] = __float2half_rn(0.f);
    }
}

// ============================================================================
extern "C" void kernel_launch(void* const* d_in, const int*, int, void* d_out, int)
{
    const float* x  = (const float*)d_in[0];
    const float* Wq = (const float*)d_in[1];
    const float* bq = (const float*)d_in[2];
    const float* Wk = (const float*)d_in[3];
    const float* bk = (const float*)d_in[4];   (void)bk;  // cancels in softmax
    const float* Wv = (const float*)d_in[5];
    const float* bv = (const float*)d_in[6];
    const float* Wo = (const float*)d_in[7];
    const float* bo = (const float*)d_in[8];
    float* out = (float*)d_out;

    h16 *xh, *xl, *wAh, *wAl, *wBh, *wBl, *gh, *gl, *qxh, *qxl, *xth, *xtl, *phh, *pll;
    float *p, *w2, *v, *rb;
    cudaGetSymbolAddress((void**)&xh,  g_xh);  cudaGetSymbolAddress((void**)&xl,  g_xl);
    cudaGetSymbolAddress((void**)&wAh, g_wAh); cudaGetSymbolAddress((void**)&wAl, g_wAl);
    cudaGetSymbolAddress((void**)&wBh, g_wBh); cudaGetSymbolAddress((void**)&wBl, g_wBl);
    cudaGetSymbolAddress((void**)&gh,  g_gh);  cudaGetSymbolAddress((void**)&gl,  g_gl);
    cudaGetSymbolAddress((void**)&qxh, g_qxh); cudaGetSymbolAddress((void**)&qxl, g_qxl);
    cudaGetSymbolAddress((void**)&xth, g_xth); cudaGetSymbolAddress((void**)&xtl, g_xtl);
    cudaGetSymbolAddress((void**)&p,   g_p);
    cudaGetSymbolAddress((void**)&phh, g_ph);  cudaGetSymbolAddress((void**)&pll, g_pl);
    cudaGetSymbolAddress((void**)&w2,  g_w2);  cudaGetSymbolAddress((void**)&v,   g_v);
    cudaGetSymbolAddress((void**)&rb,  g_rb);

    cudaFuncSetAttribute(tc_gemm<1, false, false, false, false, 1>, cudaFuncAttributeMaxDynamicSharedMemorySize, SMEM_DYN);
    cudaFuncSetAttribute(tc_gemm<1, false, false, false, false, 3>, cudaFuncAttributeMaxDynamicSharedMemorySize, SMEM_DYN);
    cudaFuncSetAttribute(tc_gemm<0, false, true,  false, false, 3>, cudaFuncAttributeMaxDynamicSharedMemorySize, SMEM_DYN);
    cudaFuncSetAttribute(tc_gemm<0, true,  false, true,  true,  2>, cudaFuncAttributeMaxDynamicSharedMemorySize, SMEM_DYN);

    // ---- prep: splits + bias vectors ---------------------------------------
    split_kernel<<<(MROWS * DM + 255) / 256, 256>>>(x, xh, xl, MROWS * DM);
    split_kernel<<<(DM * DM + 255) / 256, 256>>>(Wk, wAh,           wAl,           DM * DM);
    split_kernel<<<(DM * DM + 255) / 256, 256>>>(Wq, wBh,           wBl,           DM * DM);
    split_kernel<<<(DM * DM + 255) / 256, 256>>>(Wv, wBh + DM * DM, wBl + DM * DM, DM * DM);
    {
        dim3 blk(32, 8), grid(DM / 32, DM / 32);
        tsplit_kernel<<<grid, blk>>>(Wo, wAh + DM * DM, wAl + DM * DM, DM, DM);
    }
    wkbq_kernel<<<DM * 32 / 256, 256>>>(Wk, bq, w2);
    rb_kernel<<<DM / 256, 256>>>(Wo, bv, bo, rb);
    vvec_kernel<<<MROWS * 32 / 256, 256>>>(x, w2, v);

    // ---- GT = Wk*Wq^T ; HT = Wo^T*Wv^T-form (z=2, 1-term: corrections negligible)
    {
        dim3 grid(DM / TN, DM / TM, 2), blk(NTHREADS);
        tc_gemm<1, false, false, false, false, 1><<<grid, blk, SMEM_DYN>>>(
            wAh, wAl, wBh, wBl, nullptr, nullptr, gh, gl,
            DM, DM, DM, DM, 1.f,
            (size_t)DM * DM, (size_t)DM * DM, (size_t)DM * DM);
    }

    // ---- QG = x*GT ; XH = x*HT (z=2 batched, full 3-term) ---------------------
    {
        dim3 grid(DM / TN, MROWS / TM, 2), blk(NTHREADS);
        tc_gemm<1, false, false, false, false, 3><<<grid, blk, SMEM_DYN>>>(
            xh, xl, gh, gl, nullptr, nullptr, qxh, qxl,
            DM, DM, DM, DM, 1.f,
            0, (size_t)DM * DM, (size_t)MROWS * DM);
    }

    // ---- scores core = 0.125 * QG @ x^T (causal tile skip, 3-term) -----------
    {
        dim3 grid(SEQ / TN, SEQ / TM, BATCH), blk(NTHREADS);
        tc_gemm<0, false, true, false, false, 3><<<grid, blk, SMEM_DYN>>>(
            qxh, qxl, xh, xl, nullptr, p, nullptr, nullptr,
            DM, DM, DM, SEQ, 0.125f,
            (size_t)SEQ * DM, (size_t)SEQ * DM, (size_t)SEQ * SEQ);
    }

    // ---- XH transpose+split: [B][S][D] -> [B][D][S] ---------------------------
    {
        dim3 blk(32, 8), grid(DM / 32, SEQ / 32, BATCH);
        txsplit_kernel<<<grid, blk>>>(qxh, qxl, xth, xtl);
    }

    // ---- softmax over (scores + 0.125*v[j]) -> split f16 weights --------------
    softmax_split_kernel<<<MROWS, 256>>>(p, v, phh, pll);

    // ---- out = P @ XH + (bv*Wo + bo)  (2-term: P full precision, XH hi) -------
    {
        dim3 grid(DM / TN, SEQ / TM, BATCH), blk(NTHREADS);
        tc_gemm<0, true, false, true, true, 2><<<grid, blk, SMEM_DYN>>>(
            phh, pll, xth, xtl, rb, out, nullptr, nullptr,
            SEQ, SEQ, SEQ, DM, 1.f,
            (size_t)SEQ * SEQ, (size_t)DM * SEQ, (size_t)SEQ * DM);
    }
}

// round 11
// speedup vs baseline: 1.5131x; 1.5131x over previous
#include <cuda_runtime.h>
#include <cuda_fp16.h>
#include <math_constants.h>
#include <stdint.h>

#define BATCH 4
#define SEQ   2048
#define DM    1024
#define MROWS (BATCH * SEQ)

#define LO_SCALE  2048.0f
#define INV_LO    (1.0f / 2048.0f)

// ---- GEMM tiling (proven 256-thread / 8-warp config) --------------------------
#define TM 128
#define TN 128
#define BK 64                         // f16 elems per K-chunk (128 bytes/row)
#define TILE_BYTES (128 * 128)        // 16 KB per operand tile
#define STAGE_BYTES (4 * TILE_BYTES)  // Ahi,Alo,Bhi,Blo = 64 KB
#define NSTAGE 3
#define SMEM_DYN (NSTAGE * STAGE_BYTES)   // 192 KB

typedef __half h16;

// ---- scratch (static __device__: allocation-free) ------------------------------
#define AL1K __align__(1024)
__device__ AL1K h16   g_xh [MROWS * DM];
__device__ AL1K h16   g_xl [MROWS * DM];
__device__ AL1K h16   g_wAh[2 * DM * DM];   // [Wk ; Wo^T] split hi
__device__ AL1K h16   g_wAl[2 * DM * DM];
__device__ AL1K h16   g_wBh[2 * DM * DM];   // [Wq ; Wv] split hi
__device__ AL1K h16   g_wBl[2 * DM * DM];
__device__ AL1K h16   g_gh [2 * DM * DM];   // [GT ; HT] split hi
__device__ AL1K h16   g_gl [2 * DM * DM];
__device__ AL1K h16   g_qxh[(size_t)2 * MROWS * DM];  // [QG ; XH] split hi
__device__ AL1K h16   g_qxl[(size_t)2 * MROWS * DM];
__device__ AL1K h16   g_xth[MROWS * DM];    // XH^T per batch [B][D][S]
__device__ AL1K h16   g_xtl[MROWS * DM];
__device__ AL1K float g_p  [(size_t)BATCH * SEQ * SEQ];
__device__ AL1K h16   g_ph [(size_t)BATCH * SEQ * SEQ];
__device__ AL1K h16   g_pl [(size_t)BATCH * SEQ * SEQ];
__device__ AL1K float g_w2 [DM];
__device__ AL1K float g_v  [MROWS];
__device__ AL1K float g_rb [DM];

// ---- PTX helpers -----------------------------------------------------------------
__device__ __forceinline__ uint32_t s2u(const void* p) {
    uint32_t a;
    asm("{ .reg .u64 t; cvta.to.shared.u64 t, %1; cvt.u32.u64 %0, t; }" : "=r"(a) : "l"(p));
    return a;
}
__device__ __forceinline__ void cp16(uint32_t saddr, const void* gaddr) {
    asm volatile("cp.async.cg.shared.global [%0], [%1], 16;" :: "r"(saddr), "l"(gaddr));
}
__device__ __forceinline__ void cp_commit() { asm volatile("cp.async.commit_group;"); }
__device__ __forceinline__ void cp_wait2()  { asm volatile("cp.async.wait_group 2;" ::: "memory"); }

__device__ __forceinline__ void ldm4(uint32_t* r, uint32_t addr) {
    asm volatile("ldmatrix.sync.aligned.m8n8.x4.shared.b16 {%0,%1,%2,%3}, [%4];"
                 : "=r"(r[0]), "=r"(r[1]), "=r"(r[2]), "=r"(r[3]) : "r"(addr));
}
__device__ __forceinline__ void mma_f32(float* c, const uint32_t* a, const uint32_t* b) {
    asm volatile(
        "mma.sync.aligned.m16n8k16.row.col.f32.f16.f16.f32 "
        "{%0,%1,%2,%3}, {%4,%5,%6,%7}, {%8,%9}, {%0,%1,%2,%3};"
        : "+f"(c[0]), "+f"(c[1]), "+f"(c[2]), "+f"(c[3])
        : "r"(a[0]), "r"(a[1]), "r"(a[2]), "r"(a[3]), "r"(b[0]), "r"(b[1]));
}
__device__ __forceinline__ void mma_f16(uint32_t* c, const uint32_t* a, const uint32_t* b) {
    asm volatile(
        "mma.sync.aligned.m16n8k16.row.col.f16.f16.f16.f16 "
        "{%0,%1}, {%2,%3,%4,%5}, {%6,%7}, {%0,%1};"
        : "+r"(c[0]), "+r"(c[1])
        : "r"(a[0]), "r"(a[1]), "r"(a[2]), "r"(a[3]), "r"(b[0]), "r"(b[1]));
}
__device__ __forceinline__ uint32_t pk2(float a, float b) {
    __half2 t = __floats2half2_rn(a, b);
    return *reinterpret_cast<uint32_t*>(&t);
}

// ============================================================================
// Tensor-core GEMM, 256 threads, 8 warps, warp tile 32x64 (proven config).
//   C[M,N] = scale*((Ahi+Alo/2048)[M,K] @ ((Bhi+Blo/2048)[N,K])^T)+bias
//   NTERM=3: AhBh(f32) + AhBl(f16) + AlBh(f16)
//   NTERM=2: AhBh(f32) + AlBh(f16)   (B-lo tile never loaded)
//   OUTMODE 0: fp32 out. OUTMODE 1: f16 split out (lo x2048).
//   CAUSAL: skip tiles above diagonal.  PVLIM: K truncated.  REVY: heavy first.
// ============================================================================
template<int OUTMODE, bool HAS_BIAS, bool CAUSAL, bool PVLIM, bool REVY, int NTERM>
__global__ __launch_bounds__(256, 1)
void tc_gemm(const h16* __restrict__ Ah, const h16* __restrict__ Al,
             const h16* __restrict__ Bh, const h16* __restrict__ Bl,
             const float* __restrict__ bias,
             float* __restrict__ Cf, h16* __restrict__ Ch, h16* __restrict__ Cl,
             int Kfull, int ldA, int ldB, int ldC, float scale,
             size_t sA, size_t sB, size_t sC)
{
    const int bmi = REVY ? (gridDim.y - 1 - blockIdx.y) : blockIdx.y;
    const int m0 = bmi * TM;
    const int n0 = blockIdx.x * TN;
    if (CAUSAL && n0 > m0) return;

    const int z = blockIdx.z;
    Ah += (size_t)z * sA;  Al += (size_t)z * sA;
    Bh += (size_t)z * sB;  Bl += (size_t)z * sB;

    extern __shared__ char dsm[];
    const uint32_t smem = s2u(dsm);

    const int tid  = threadIdx.x;
    const int wid  = tid >> 5;
    const int lane = tid & 31;
    const int wm   = wid & 3;    // 4 warp-rows  (32 M each)
    const int wn   = wid >> 2;   // 2 warp-cols  (64 N each)

    const int nchunk = PVLIM ? (m0 + TM) / BK : Kfull / BK;

    // ---- loader: each thread = half a row (4x16B segs) of each tile -----------
    const int lrow = tid >> 1;            // 0..127
    const int sb   = (tid & 1) * 4;       // seg base 0 or 4
    const char* gp[4];
    uint32_t    so[4][4];
    {
        const h16* bases[4] = {Ah, Al, Bh, Bl};
        #pragma unroll
        for (int t = 0; t < 4; t++) {
            const int off = (t < 2) ? m0 : n0;
            const int ld  = (t < 2) ? ldA : ldB;
            gp[t] = (const char*)(bases[t] + (size_t)(off + lrow) * ld);
            #pragma unroll
            for (int j = 0; j < 4; j++) {
                const int seg = sb + j;
                so[t][j] = (uint32_t)(t * TILE_BYTES + lrow * 128 +
                                      ((seg ^ (lrow & 7)) << 4));
            }
        }
    }

    auto load_stage = [&](int slot, int chunk) {
        if (chunk < nchunk) {
            const uint32_t s0 = smem + slot * STAGE_BYTES;
            const size_t goff = (size_t)chunk * 128;
            #pragma unroll
            for (int t = 0; t < 4; t++) {
                if (t == 3 && NTERM < 3) continue;   // B-lo unused
                #pragma unroll
                for (int j = 0; j < 4; j++)
                    cp16(s0 + so[t][j], gp[t] + goff + (size_t)(sb + j) * 16);
            }
        }
        cp_commit();
    };

    float    accf[2][8][4];
    uint32_t acch[2][8][2];
    #pragma unroll
    for (int a = 0; a < 2; a++)
        #pragma unroll
        for (int b = 0; b < 8; b++) {
            #pragma unroll
            for (int c = 0; c < 4; c++) accf[a][b][c] = 0.f;
            acch[a][b][0] = 0u; acch[a][b][1] = 0u;
        }

    load_stage(0, 0);
    load_stage(1, 1);
    load_stage(2, 2);

    const int a_r  = lane & 15;
    const int a_kh = lane >> 4;
    const int b_nl = ((lane >> 4) & 1) * 8 + (lane & 7);
    const int b_kh = (lane >> 3) & 1;

    for (int i = 0; i < nchunk; i++) {
        cp_wait2();
        __syncthreads();
        const uint32_t s0 = smem + (i % 3) * STAGE_BYTES;

        #pragma unroll
        for (int kk = 0; kk < 4; kk++) {
            uint32_t ahf[2][4], alf[2][4], bhf[4][4], blf[4][4];
            #pragma unroll
            for (int mt = 0; mt < 2; mt++) {
                const int row = wm * 32 + mt * 16 + a_r;
                const int seg = kk * 2 + a_kh;
                const uint32_t off = (uint32_t)(row * 128 + ((seg ^ (row & 7)) << 4));
                ldm4(ahf[mt], s0 + 0 * TILE_BYTES + off);
                ldm4(alf[mt], s0 + 1 * TILE_BYTES + off);
            }
            #pragma unroll
            for (int p = 0; p < 4; p++) {
                const int row = wn * 64 + p * 16 + b_nl;
                const int seg = kk * 2 + b_kh;
                const uint32_t off = (uint32_t)(row * 128 + ((seg ^ (row & 7)) << 4));
                ldm4(bhf[p], s0 + 2 * TILE_BYTES + off);
                if (NTERM >= 3) ldm4(blf[p], s0 + 3 * TILE_BYTES + off);
            }
            // main term (f32 acc)
            #pragma unroll
            for (int mt = 0; mt < 2; mt++)
                #pragma unroll
                for (int nt = 0; nt < 8; nt++)
                    mma_f32(accf[mt][nt], ahf[mt], &bhf[nt >> 1][(nt & 1) * 2]);
            // correction terms (f16 acc; lo operands pre-scaled x2048)
            if (NTERM >= 3) {
                #pragma unroll
                for (int mt = 0; mt < 2; mt++)
                    #pragma unroll
                    for (int nt = 0; nt < 8; nt++)
                        mma_f16(acch[mt][nt], ahf[mt], &blf[nt >> 1][(nt & 1) * 2]);
            }
            #pragma unroll
            for (int mt = 0; mt < 2; mt++)
                #pragma unroll
                for (int nt = 0; nt < 8; nt++)
                    mma_f16(acch[mt][nt], alf[mt], &bhf[nt >> 1][(nt & 1) * 2]);
        }
        __syncthreads();
        load_stage(i % 3, i + 3);
    }

    #pragma unroll
    for (int mt = 0; mt < 2; mt++) {
        #pragma unroll
        for (int h = 0; h < 2; h++) {
            const int row = m0 + wm * 32 + mt * 16 + (lane >> 2) + 8 * h;
            #pragma unroll
            for (int nt = 0; nt < 8; nt++) {
                const int col = n0 + wn * 64 + nt * 8 + (lane & 3) * 2;
                const __half2 hc = *reinterpret_cast<const __half2*>(&acch[mt][nt][h]);
                float v0 = (accf[mt][nt][2 * h + 0] + __low2float(hc)  * INV_LO) * scale;
                float v1 = (accf[mt][nt][2 * h + 1] + __high2float(hc) * INV_LO) * scale;
                if (HAS_BIAS) {
                    const float2 bb = *reinterpret_cast<const float2*>(bias + col);
                    v0 += bb.x; v1 += bb.y;
                }
                if (OUTMODE == 0) {
                    *reinterpret_cast<float2*>(
                        Cf + (size_t)z * sC + (size_t)row * ldC + col) =
                        make_float2(v0, v1);
                } else {
                    float h0 = __half2float(__float2half_rn(v0));
                    float h1 = __half2float(__float2half_rn(v1));
                    *reinterpret_cast<uint32_t*>(
                        Ch + (size_t)z * sC + (size_t)row * ldC + col) = pk2(h0, h1);
                    *reinterpret_cast<uint32_t*>(
                        Cl + (size_t)z * sC + (size_t)row * ldC + col) =
                        pk2((v0 - h0) * LO_SCALE, (v1 - h1) * LO_SCALE);
                }
            }
        }
    }
}

// ============================================================================
// prep kernels (all lo outputs pre-scaled x2048)
// ============================================================================
__global__ void split_kernel(const float* __restrict__ in,
                             h16* __restrict__ oh, h16* __restrict__ ol, int n)
{
    int i = blockIdx.x * blockDim.x + threadIdx.x;
    if (i >= n) return;
    float v = in[i];
    h16 h = __float2half_rn(v);
    oh[i] = h;
    ol[i] = __float2half_rn((v - __half2float(h)) * LO_SCALE);
}

__global__ void tsplit_kernel(const float* __restrict__ in,
                              h16* __restrict__ oh, h16* __restrict__ ol,
                              int R, int C)
{
    __shared__ float t[32][33];
    const int c0 = blockIdx.x * 32, r0 = blockIdx.y * 32;
    const int tx = threadIdx.x, ty = threadIdx.y;
    #pragma unroll
    for (int k = 0; k < 4; k++)
        t[ty + 8 * k][tx] = in[(size_t)(r0 + ty + 8 * k) * C + c0 + tx];
    __syncthreads();
    #pragma unroll
    for (int k = 0; k < 4; k++) {
        float v = t[tx][ty + 8 * k];
        h16 h = __float2half_rn(v);
        size_t o = (size_t)(c0 + ty + 8 * k) * R + r0 + tx;
        oh[o] = h;
        ol[o] = __float2half_rn((v - __half2float(h)) * LO_SCALE);
    }
}

// XH transpose+split: reads XH = hi + lo/2048 at rows [MROWS + b*SEQ + s], ld=DM
__global__ void txsplit_kernel(const h16* __restrict__ qh, const h16* __restrict__ ql,
                               h16* __restrict__ oh, h16* __restrict__ ol)
{
    __shared__ float t[32][33];
    const int z = blockIdx.z;
    const int d0 = blockIdx.x * 32, s0 = blockIdx.y * 32;
    const int tx = threadIdx.x, ty = threadIdx.y;
    #pragma unroll
    for (int k = 0; k < 4; k++) {
        size_t idx = (size_t)(MROWS + z * SEQ + s0 + ty + 8 * k) * DM + d0 + tx;
        t[ty + 8 * k][tx] = __half2float(qh[idx]) + __half2float(ql[idx]) * INV_LO;
    }
    __syncthreads();
    #pragma unroll
    for (int k = 0; k < 4; k++) {
        float v = t[tx][ty + 8 * k];
        h16 h = __float2half_rn(v);
        size_t o = (size_t)z * DM * SEQ + (size_t)(d0 + ty + 8 * k) * SEQ + s0 + tx;
        oh[o] = h;
        ol[o] = __float2half_rn((v - __half2float(h)) * LO_SCALE);
    }
}

__global__ void wkbq_kernel(const float* __restrict__ Wk, const float* __restrict__ bq,
                            float* __restrict__ w2)
{
    int w = (blockIdx.x * blockDim.x + threadIdx.x) >> 5;
    int lane = threadIdx.x & 31;
    if (w >= DM) return;
    float s = 0.f;
    for (int e = lane; e < DM; e += 32) s += Wk[(size_t)w * DM + e] * bq[e];
    #pragma unroll
    for (int o = 16; o > 0; o >>= 1) s += __shfl_down_sync(0xffffffffu, s, o);
    if (lane == 0) w2[w] = s;
}

__global__ void rb_kernel(const float* __restrict__ Wo, const float* __restrict__ bv,
                          const float* __restrict__ bo, float* __restrict__ rb)
{
    int d = blockIdx.x * blockDim.x + threadIdx.x;
    if (d >= DM) return;
    float s = 0.f;
    for (int e = 0; e < DM; e++) s += bv[e] * Wo[(size_t)e * DM + d];
    rb[d] = s + bo[d];
}

__global__ void vvec_kernel(const float* __restrict__ x, const float* __restrict__ w2,
                            float* __restrict__ v)
{
    int w = (blockIdx.x * blockDim.x + threadIdx.x) >> 5;
    int lane = threadIdx.x & 31;
    if (w >= MROWS) return;
    float s = 0.f;
    for (int d = lane; d < DM; d += 32) s += x[(size_t)w * DM + d] * w2[d];
    #pragma unroll
    for (int o = 16; o > 0; o >>= 1) s += __shfl_down_sync(0xffffffffu, s, o);
    if (lane == 0) v[w] = s;
}

__global__ __launch_bounds__(256)
void softmax_split_kernel(float* __restrict__ P, const float* __restrict__ V,
                          h16* __restrict__ Ph, h16* __restrict__ Pl)
{
    const int rowi = blockIdx.x;
    const int b = rowi / SEQ, q = rowi % SEQ;
    const size_t off = (size_t)b * SEQ * SEQ + (size_t)q * SEQ;
    float* p = P + off;
    const float* vv = V + (size_t)b * SEQ;
    h16* ph = Ph + off;
    h16* pl = Pl + off;
    const int n = q + 1;

    __shared__ float red[256];
    const int tid = threadIdx.x;

    float mx = -CUDART_INF_F;
    for (int k = tid; k < n; k += 256) mx = fmaxf(mx, p[k] + 0.125f * vv[k]);
    red[tid] = mx; __syncthreads();
    #pragma unroll
    for (int s = 128; s > 0; s >>= 1) {
        if (tid < s) red[tid] = fmaxf(red[tid], red[tid + s]);
        __syncthreads();
    }
    mx = red[0]; __syncthreads();

    float sum = 0.f;
    for (int k = tid; k < n; k += 256) {
        float e = expf(p[k] + 0.125f * vv[k] - mx);
        p[k] = e;
        sum += e;
    }
    red[tid] = sum; __syncthreads();
    #pragma unroll
    for (int s = 128; s > 0; s >>= 1) {
        if (tid < s) red[tid] += red[tid + s];
        __syncthreads();
    }
    const float inv = 1.f / red[0];

    for (int k = tid; k < n; k += 256) {
        float w = p[k] * inv;
        h16 h = __float2half_rn(w);
        ph[k] = h;
        pl[k] = __float2half_rn((w - __half2float(h)) * LO_SCALE);
    }
    const int fillEnd = ((q >> 7) + 1) << 7;
    for (int k = n + tid; k < fillEnd; k += 256) {
        ph[k] = __float2half_rn(0.f);
        pl[k] = __float2half_rn(0.f);
    }
}

// ============================================================================
extern "C" void kernel_launch(void* const* d_in, const int*, int, void* d_out, int)
{
    const float* x  = (const float*)d_in[0];
    const float* Wq = (const float*)d_in[1];
    const float* bq = (const float*)d_in[2];
    const float* Wk = (const float*)d_in[3];
    const float* bk = (const float*)d_in[4];   (void)bk;  // cancels in softmax
    const float* Wv = (const float*)d_in[5];
    const float* bv = (const float*)d_in[6];
    const float* Wo = (const float*)d_in[7];
    const float* bo = (const float*)d_in[8];
    float* out = (float*)d_out;

    h16 *xh, *xl, *wAh, *wAl, *wBh, *wBl, *gh, *gl, *qxh, *qxl, *xth, *xtl, *phh, *pll;
    float *p, *w2, *v, *rb;
    cudaGetSymbolAddress((void**)&xh,  g_xh);  cudaGetSymbolAddress((void**)&xl,  g_xl);
    cudaGetSymbolAddress((void**)&wAh, g_wAh); cudaGetSymbolAddress((void**)&wAl, g_wAl);
    cudaGetSymbolAddress((void**)&wBh, g_wBh); cudaGetSymbolAddress((void**)&wBl, g_wBl);
    cudaGetSymbolAddress((void**)&gh,  g_gh);  cudaGetSymbolAddress((void**)&gl,  g_gl);
    cudaGetSymbolAddress((void**)&qxh, g_qxh); cudaGetSymbolAddress((void**)&qxl, g_qxl);
    cudaGetSymbolAddress((void**)&xth, g_xth); cudaGetSymbolAddress((void**)&xtl, g_xtl);
    cudaGetSymbolAddress((void**)&p,   g_p);
    cudaGetSymbolAddress((void**)&phh, g_ph);  cudaGetSymbolAddress((void**)&pll, g_pl);
    cudaGetSymbolAddress((void**)&w2,  g_w2);  cudaGetSymbolAddress((void**)&v,   g_v);
    cudaGetSymbolAddress((void**)&rb,  g_rb);

    cudaFuncSetAttribute(tc_gemm<1, false, false, false, false, 3>, cudaFuncAttributeMaxDynamicSharedMemorySize, SMEM_DYN);
    cudaFuncSetAttribute(tc_gemm<1, false, false, false, false, 2>, cudaFuncAttributeMaxDynamicSharedMemorySize, SMEM_DYN);
    cudaFuncSetAttribute(tc_gemm<0, false, true,  false, false, 2>, cudaFuncAttributeMaxDynamicSharedMemorySize, SMEM_DYN);
    cudaFuncSetAttribute(tc_gemm<0, true,  false, true,  true,  2>, cudaFuncAttributeMaxDynamicSharedMemorySize, SMEM_DYN);

    // ---- prep: splits + bias vectors ---------------------------------------
    split_kernel<<<(MROWS * DM + 255) / 256, 256>>>(x, xh, xl, MROWS * DM);
    split_kernel<<<(DM * DM + 255) / 256, 256>>>(Wk, wAh,           wAl,           DM * DM);
    split_kernel<<<(DM * DM + 255) / 256, 256>>>(Wq, wBh,           wBl,           DM * DM);
    split_kernel<<<(DM * DM + 255) / 256, 256>>>(Wv, wBh + DM * DM, wBl + DM * DM, DM * DM);
    {
        dim3 blk(32, 8), grid(DM / 32, DM / 32);
        tsplit_kernel<<<grid, blk>>>(Wo, wAh + DM * DM, wAl + DM * DM, DM, DM);
    }
    wkbq_kernel<<<DM * 32 / 256, 256>>>(Wk, bq, w2);
    rb_kernel<<<DM / 256, 256>>>(Wo, bv, bo, rb);
    vvec_kernel<<<MROWS * 32 / 256, 256>>>(x, w2, v);

    // ---- GT = Wk*Wq^T ; HT = Wo^T*Wv^T-form (z=2, FULL 3-term: error-amplified)
    {
        dim3 grid(DM / TN, DM / TM, 2), blk(256);
        tc_gemm<1, false, false, false, false, 3><<<grid, blk, SMEM_DYN>>>(
            wAh, wAl, wBh, wBl, nullptr, nullptr, gh, gl,
            DM, DM, DM, DM, 1.f,
            (size_t)DM * DM, (size_t)DM * DM, (size_t)DM * DM);
    }

    // ---- QG = x*GT ; XH = x*HT (z=2 batched, 2-term: drop xh*GTl) -------------
    {
        dim3 grid(DM / TN, MROWS / TM, 2), blk(256);
        tc_gemm<1, false, false, false, false, 2><<<grid, blk, SMEM_DYN>>>(
            xh, xl, gh, gl, nullptr, nullptr, qxh, qxl,
            DM, DM, DM, DM, 1.f,
            0, (size_t)DM * DM, (size_t)MROWS * DM);
    }

    // ---- scores core = 0.125 * QG @ x^T (causal, 2-term: drop QGh*xl) ---------
    {
        dim3 grid(SEQ / TN, SEQ / TM, BATCH), blk(256);
        tc_gemm<0, false, true, false, false, 2><<<grid, blk, SMEM_DYN>>>(
            qxh, qxl, xh, xl, nullptr, p, nullptr, nullptr,
            DM, DM, DM, SEQ, 0.125f,
            (size_t)SEQ * DM, (size_t)SEQ * DM, (size_t)SEQ * SEQ);
    }

    // ---- XH transpose+split: [B][S][D] -> [B][D][S] ---------------------------
    {
        dim3 blk(32, 8), grid(DM / 32, SEQ / 32, BATCH);
        txsplit_kernel<<<grid, blk>>>(qxh, qxl, xth, xtl);
    }

    // ---- softmax over (scores + 0.125*v[j]) -> split f16 weights --------------
    softmax_split_kernel<<<MROWS, 256>>>(p, v, phh, pll);

    // ---- out = P @ XH + (bv*Wo + bo)  (2-term: drop Ph*XHl) --------------------
    {
        dim3 grid(DM / TN, SEQ / TM, BATCH), blk(256);
        tc_gemm<0, true, false, true, true, 2><<<grid, blk, SMEM_DYN>>>(
            phh, pll, xth, xtl, rb, out, nullptr, nullptr,
            SEQ, SEQ, SEQ, DM, 1.f,
            (size_t)SEQ * SEQ, (size_t)DM * SEQ, (size_t)SEQ * DM);
    }
}